// round 9
// baseline (speedup 1.0000x reference)
#include <cuda_runtime.h>
#include <cstdint>

#define DDIM 64
#define KCODES 1024
#define NTOK 131072
#define TM 128
#define NTHREADS 256
#define NCHUNKS 16
#define CCHUNK 64
#define CAP 6
#define MARGIN 0.008f

#define ROWW 72                         // words per fragment row (288B, bank-safe)
#define CHUNK_BYTES (CCHUNK * ROWW * 4) // 18432

// ---------------- smem layout (bytes) ----------------
#define OFF_XF   0                      // float [128][65] = 33280
#define OFF_CN   33280                  // float [1024]    = 4096
#define OFF_CAND 37376                  // int [128][4][6] = 12288
#define OFF_XNS  49664                  // float [128]
#define OFF_WIX  50176                  // int [128]
#define OFF_OFL  50688                  // int [128]
#define OFF_B    51200                  // 3 x 18432
#define SMEM_BYTES (OFF_B + 3 * CHUNK_BYTES)   // 106496

__device__ float g_cn[KCODES];
__device__ __align__(256) uint32_t g_bT[KCODES * ROWW];  // tf32, fragment order (R5-R7 verified)

__device__ __forceinline__ uint32_t f2tf(float x) {
    uint32_t r;
    asm("cvt.rna.tf32.f32 %0, %1;" : "=r"(r) : "f"(x));
    return r;
}

__global__ void vq_prep(const float* __restrict__ cb) {
    int r = blockIdx.x * blockDim.x + threadIdx.x;
    if (r >= KCODES) return;
    const float* cr = cb + r * DDIM;
    float acc = 0.f;
#pragma unroll
    for (int d = 0; d < DDIM; d++) acc = __fadd_rn(acc, __fmul_rn(cr[d], cr[d]));
    g_cn[r] = acc;
    const int qoff[4] = {0, 16, 36, 52};
#pragma unroll
    for (int q = 0; q < 4; q++)
#pragma unroll
        for (int kc = 0; kc < 8; kc++) {
            g_bT[r * ROWW + qoff[q] + kc * 2 + 0] = f2tf(cr[kc * 8 + q]);
            g_bT[r * ROWW + qoff[q] + kc * 2 + 1] = f2tf(cr[kc * 8 + q + 4]);
        }
#pragma unroll
    for (int p = 68; p < 72; p++) g_bT[r * ROWW + p] = 0;
}

__device__ __forceinline__ void mma_tf32(float* c, const uint32_t* a,
                                         uint32_t b0, uint32_t b1) {
    asm volatile(
        "mma.sync.aligned.m16n8k8.row.col.f32.tf32.tf32.f32 "
        "{%0,%1,%2,%3}, {%4,%5,%6,%7}, {%8,%9}, {%0,%1,%2,%3};"
        : "+f"(c[0]), "+f"(c[1]), "+f"(c[2]), "+f"(c[3])
        : "r"(a[0]), "r"(a[1]), "r"(a[2]), "r"(a[3]), "r"(b0), "r"(b1));
}
__device__ __forceinline__ uint4 lds128(uint32_t a) {
    uint4 v;
    asm volatile("ld.shared.v4.u32 {%0,%1,%2,%3}, [%4];"
                 : "=r"(v.x), "=r"(v.y), "=r"(v.z), "=r"(v.w) : "r"(a));
    return v;
}
__device__ __forceinline__ uint32_t smem_u32(const void* p) {
    uint32_t a;
    asm("{ .reg .u64 t; cvta.to.shared.u64 t, %1; cvt.u32.u64 %0, t; }" : "=r"(a) : "l"(p));
    return a;
}
__device__ __forceinline__ void issue_chunk(uint32_t dst, const char* src) {
#pragma unroll
    for (int k = 0; k < 5; k++) {
        int off = (threadIdx.x + k * NTHREADS) * 16;
        if (off < CHUNK_BYTES)
            asm volatile("cp.async.ca.shared.global [%0], [%1], 16;"
                         :: "r"(dst + off), "l"(src + off) : "memory");
    }
    asm volatile("cp.async.commit_group;" ::: "memory");
}

// exact rescore: bit-matches reference (verified R2/R4-R7)
__device__ __forceinline__ float exact_d2(const float* __restrict__ cb,
                                          const float* __restrict__ xrow,
                                          float xn, float cnk, int k) {
    const float4* cr = (const float4*)(cb + k * DDIM);
    float s = 0.f;
#pragma unroll 4
    for (int i = 0; i < 16; i++) {
        float4 v = cr[i];
        s = __fmaf_rn(xrow[4 * i + 0], v.x, s);
        s = __fmaf_rn(xrow[4 * i + 1], v.y, s);
        s = __fmaf_rn(xrow[4 * i + 2], v.z, s);
        s = __fmaf_rn(xrow[4 * i + 3], v.w, s);
    }
    return __fadd_rn(__fsub_rn(xn, __fmul_rn(2.0f, s)), cnk);
}

__global__ __launch_bounds__(NTHREADS, 1)   // <-- the fix: 255-reg budget, no spills
void vq_main(const float* __restrict__ h, const float* __restrict__ cb,
             float* __restrict__ outZ, float* __restrict__ outQ) {
    extern __shared__ char smem[];
    float* Xf   = (float*)(smem + OFF_XF);
    float* Cn   = (float*)(smem + OFF_CN);
    int*   cand = (int*)(smem + OFF_CAND);
    float* xns  = (float*)(smem + OFF_XNS);
    int*   wix  = (int*)(smem + OFF_WIX);
    int*   ofl  = (int*)(smem + OFF_OFL);
    const uint32_t sbase = smem_u32(smem);

    const int tid = threadIdx.x;
    const int wid = tid >> 5;
    const int lid = tid & 31;
    const int g = lid >> 2;
    const int q = lid & 3;
    const int tw = wid * 16;
    const int n0 = blockIdx.x * TM;
    const int b = n0 >> 12;
    const long base = (long)b * 262144 + (n0 & 4095);

#pragma unroll
    for (int c = 0; c < 3; c++)
        issue_chunk(sbase + OFF_B + c * CHUNK_BYTES, (const char*)g_bT + c * CHUNK_BYTES);

    for (int i = tid; i < 64 * 32; i += NTHREADS) {
        int d = i >> 5, t4 = i & 31;
        float4 v = *(const float4*)(h + base + (long)d * 4096 + t4 * 4);
        Xf[(t4 * 4 + 0) * 65 + d] = v.x;
        Xf[(t4 * 4 + 1) * 65 + d] = v.y;
        Xf[(t4 * 4 + 2) * 65 + d] = v.z;
        Xf[(t4 * 4 + 3) * 65 + d] = v.w;
    }
    for (int i = tid; i < KCODES; i += NTHREADS) Cn[i] = g_cn[i];
    if (tid < 128) ofl[tid] = 0;
    __syncthreads();

    if (tid < 128) {
        float acc = 0.f;
#pragma unroll
        for (int d = 0; d < 64; d++) {
            float xv = Xf[tid * 65 + d];
            acc = __fadd_rn(acc, __fmul_rn(xv, xv));
        }
        xns[tid] = acc;
    }

    uint32_t afr[32];
    {
        const float* xr = &Xf[(tw + g) * 65];
#pragma unroll
        for (int kc = 0; kc < 8; kc++) {
            int d0 = kc * 8 + q;
            afr[kc * 4 + 0] = f2tf(xr[d0]);
            afr[kc * 4 + 1] = f2tf(xr[8 * 65 + d0]);
            afr[kc * 4 + 2] = f2tf(xr[d0 + 4]);
            afr[kc * 4 + 3] = f2tf(xr[8 * 65 + d0 + 4]);
        }
    }
    __syncthreads();

    const int tok0 = tw + g, tok1 = tw + g + 8;
    const float xn0 = xns[tok0], xn1 = xns[tok1];
    float best0 = 3.4e38f, best1 = 3.4e38f;
    int cnt0 = 0, cnt1 = 0;
    const uint32_t qoffB = (uint32_t)(q * 64 + (q >> 1) * 16);

#pragma unroll 1
    for (int c = 0; c < NCHUNKS; c++) {
        if (c < 14)       asm volatile("cp.async.wait_group 2;" ::: "memory");
        else if (c == 14) asm volatile("cp.async.wait_group 1;" ::: "memory");
        else              asm volatile("cp.async.wait_group 0;" ::: "memory");
        __syncthreads();

        const uint32_t bb = sbase + OFF_B + (c % 3) * CHUNK_BYTES;
        const int cbase = c * CCHUNK;

#pragma unroll
        for (int jp = 0; jp < 4; jp++) {
            const int j0 = jp * 2, j1 = jp * 2 + 1;
            uint32_t a0 = bb + (uint32_t)((j0 * 8 + g) * 288) + qoffB;
            uint32_t a1 = a0 + 8 * 288;

            float ac0[4] = {0.f, 0.f, 0.f, 0.f};
            float ac1[4] = {0.f, 0.f, 0.f, 0.f};
            uint4 v0, v1;
            v0 = lds128(a0);
            v1 = lds128(a1);
            mma_tf32(ac0, afr + 0,  v0.x, v0.y);
            mma_tf32(ac1, afr + 0,  v1.x, v1.y);
            mma_tf32(ac0, afr + 4,  v0.z, v0.w);
            mma_tf32(ac1, afr + 4,  v1.z, v1.w);
            v0 = lds128(a0 + 16);
            v1 = lds128(a1 + 16);
            mma_tf32(ac0, afr + 8,  v0.x, v0.y);
            mma_tf32(ac1, afr + 8,  v1.x, v1.y);
            mma_tf32(ac0, afr + 12, v0.z, v0.w);
            mma_tf32(ac1, afr + 12, v1.z, v1.w);
            v0 = lds128(a0 + 32);
            v1 = lds128(a1 + 32);
            mma_tf32(ac0, afr + 16, v0.x, v0.y);
            mma_tf32(ac1, afr + 16, v1.x, v1.y);
            mma_tf32(ac0, afr + 20, v0.z, v0.w);
            mma_tf32(ac1, afr + 20, v1.z, v1.w);
            v0 = lds128(a0 + 48);
            v1 = lds128(a1 + 48);
            mma_tf32(ac0, afr + 24, v0.x, v0.y);
            mma_tf32(ac1, afr + 24, v1.x, v1.y);
            mma_tf32(ac0, afr + 28, v0.z, v0.w);
            mma_tf32(ac1, afr + 28, v1.z, v1.w);

#pragma unroll
            for (int s = 0; s < 2; s++) {
                const float* ac = s ? ac1 : ac0;
                int k0 = cbase + (s ? j1 : j0) * 8 + q * 2;
                float2 cn2 = *(const float2*)&Cn[k0];
                float a00 = xn0 - 2.0f * ac[0] + cn2.x;
                float a01 = xn0 - 2.0f * ac[1] + cn2.y;
                float a10 = xn1 - 2.0f * ac[2] + cn2.x;
                float a11 = xn1 - 2.0f * ac[3] + cn2.y;
                if (fminf(a00, a01) < best0 + MARGIN) {
                    if (a00 < best0 + MARGIN) {
                        if (cnt0 < CAP) cand[(tok0 * 4 + q) * CAP + cnt0] = k0; else ofl[tok0] = 1;
                        cnt0++;
                    }
                    if (a01 < best0 + MARGIN) {
                        if (cnt0 < CAP) cand[(tok0 * 4 + q) * CAP + cnt0] = k0 + 1; else ofl[tok0] = 1;
                        cnt0++;
                    }
                    best0 = fminf(best0, fminf(a00, a01));
                }
                if (fminf(a10, a11) < best1 + MARGIN) {
                    if (a10 < best1 + MARGIN) {
                        if (cnt1 < CAP) cand[(tok1 * 4 + q) * CAP + cnt1] = k0; else ofl[tok1] = 1;
                        cnt1++;
                    }
                    if (a11 < best1 + MARGIN) {
                        if (cnt1 < CAP) cand[(tok1 * 4 + q) * CAP + cnt1] = k0 + 1; else ofl[tok1] = 1;
                        cnt1++;
                    }
                    best1 = fminf(best1, fminf(a10, a11));
                }
            }
        }

        best0 = fminf(best0, __shfl_xor_sync(0xffffffffu, best0, 1));
        best0 = fminf(best0, __shfl_xor_sync(0xffffffffu, best0, 2));
        best1 = fminf(best1, __shfl_xor_sync(0xffffffffu, best1, 1));
        best1 = fminf(best1, __shfl_xor_sync(0xffffffffu, best1, 2));

        __syncthreads();
        if (c + 3 < NCHUNKS)
            issue_chunk(sbase + OFF_B + ((c + 3) % 3) * CHUNK_BYTES,
                        (const char*)g_bT + (c + 3) * CHUNK_BYTES);
    }

    // exact rescore (bit-matches reference); quad combine, lowest-index tie-break
#pragma unroll
    for (int s = 0; s < 2; s++) {
        int t = s ? tok1 : tok0;
        int cnt = s ? cnt1 : cnt0;
        const float* xrow = &Xf[t * 65];
        float xn = s ? xn1 : xn0;
        float bv = 3.4e38f;
        int bi = 0x7fffffff;
        if (ofl[t]) {
            for (int k = q; k < KCODES; k += 4) {
                float d2 = exact_d2(cb, xrow, xn, Cn[k], k);
                if (d2 < bv || (d2 == bv && k < bi)) { bv = d2; bi = k; }
            }
        } else {
            for (int i = 0; i < cnt; i++) {
                int k = cand[(t * 4 + q) * CAP + i];
                float d2 = exact_d2(cb, xrow, xn, Cn[k], k);
                if (d2 < bv || (d2 == bv && k < bi)) { bv = d2; bi = k; }
            }
        }
#pragma unroll
        for (int off = 1; off < 4; off <<= 1) {
            float ov = __shfl_xor_sync(0xffffffffu, bv, off);
            int oi = __shfl_xor_sync(0xffffffffu, bi, off);
            if (ov < bv || (ov == bv && oi < bi)) { bv = ov; bi = oi; }
        }
        if (q == 0) {
            wix[t] = bi;
            if (outZ) outZ[n0 + t] = (float)bi;
        }
    }
    __syncthreads();

    if (outQ) {
        for (int i = tid; i < 128 * 16; i += NTHREADS) {
            int tt = i >> 4, c4 = i & 15;
            float4 v = *(const float4*)&cb[wix[tt] * DDIM + c4 * 4];
            *(float4*)&outQ[(long)(n0 + tt) * DDIM + c4 * 4] = v;
        }
    }
}

extern "C" void kernel_launch(void* const* d_in, const int* in_sizes, int n_in,
                              void* d_out, int out_size) {
    const float* h = (const float*)d_in[0];
    const float* cb = (const float*)d_in[1];
    float* out = (float*)d_out;

    float* outZ = nullptr;
    float* outQ = nullptr;
    if (out_size >= NTOK + NTOK * DDIM) { outZ = out; outQ = out + NTOK; }
    else if (out_size == NTOK * DDIM)   { outQ = out; }
    else                                { outZ = out; }

    cudaFuncSetAttribute(vq_main, cudaFuncAttributeMaxDynamicSharedMemorySize, SMEM_BYTES);
    vq_prep<<<4, 256>>>(cb);
    vq_main<<<NTOK / TM, NTHREADS, SMEM_BYTES>>>(h, cb, outZ, outQ);
}

// round 10
// speedup vs baseline: 6.1089x; 6.1089x over previous
#include <cuda_runtime.h>
#include <cstdint>

#define DDIM 64
#define KCODES 1024
#define NTOK 131072
#define TM 128
#define NTHREADS 512
#define PASSES 4
#define CPASS 256
#define CAP 10
#define MARGIN 0.035f
#define XSCALE (127.0f / 6.0f)

// ---------------- smem layout (bytes) ----------------
#define OFF_XF    0        // f32 [128][65]  = 33280
#define OFF_XI8   33280    // i32 [16][128]  = 8192   (packed int8 x, dq-major)
#define OFF_CS    41472    // i32 [16][256]  = 16384  (packed int8 codes, per pass)
#define OFF_CN    57856    // f32 [1024]     = 4096
#define OFF_CAND  61952    // int [16][128][10] = 81920
#define OFF_REDV  143872   // f32 [16][128]  = 8192
#define OFF_GB    152064   // f32 [128]      = 512
#define OFF_RV2   152576   // f32 [4][128]   = 2048
#define OFF_RI2   154624   // int [4][128]   = 2048
#define OFF_XNS   156672   // f32 [128]
#define OFF_WIX   157184   // int [128]
#define OFF_SCNT  157696   // u8  [16][128]  = 2048
#define OFF_SOFL  159744   // u8  [16][128]  = 2048
#define OFF_TOFL  161792   // u8  [128]
#define SMEM_BYTES 161920

__device__ unsigned g_cmaxbits;              // atomicMax of |c| bits (idempotent across replays)
__device__ float g_inv;                      // 1/(sx*sc)
__device__ float g_cn[KCODES];               // ||c||^2, sequential order (bit-matches ref)
__device__ __align__(16) int g_ci8[16 * KCODES];  // packed int8 codebook [dq][k]

__global__ void vq_prep1(const float* __restrict__ cb) {
    int i = blockIdx.x * blockDim.x + threadIdx.x;
    float m = 0.f;
    for (int j = i; j < KCODES * DDIM; j += gridDim.x * blockDim.x)
        m = fmaxf(m, fabsf(cb[j]));
    atomicMax(&g_cmaxbits, __float_as_uint(m));  // positive floats: uint order == float order
}

__global__ void vq_prep2(const float* __restrict__ cb) {
    int k = blockIdx.x * blockDim.x + threadIdx.x;
    if (k >= KCODES) return;
    float cmax = __uint_as_float(g_cmaxbits);
    float sc = 127.0f / cmax;
    if (k == 0) g_inv = 1.0f / (XSCALE * sc);
    const float* cr = cb + k * DDIM;
    float acc = 0.f;
#pragma unroll
    for (int d = 0; d < DDIM; d++) acc = __fadd_rn(acc, __fmul_rn(cr[d], cr[d]));
    g_cn[k] = acc;
#pragma unroll
    for (int dq = 0; dq < 16; dq++) {
        uint32_t p = 0;
#pragma unroll
        for (int e = 0; e < 4; e++) {
            int v = __float2int_rn(cr[dq * 4 + e] * sc);
            v = max(-127, min(127, v));
            p |= ((uint32_t)(uint8_t)(char)v) << (8 * e);
        }
        g_ci8[dq * KCODES + k] = (int)p;
    }
}

__device__ __forceinline__ uint32_t smem_u32(const void* p) {
    uint32_t a;
    asm("{ .reg .u64 t; cvta.to.shared.u64 t, %1; cvt.u32.u64 %0, t; }" : "=r"(a) : "l"(p));
    return a;
}
__device__ __forceinline__ uint4 lds128(uint32_t a) {
    uint4 v;
    asm volatile("ld.shared.v4.u32 {%0,%1,%2,%3}, [%4];"
                 : "=r"(v.x), "=r"(v.y), "=r"(v.z), "=r"(v.w) : "r"(a));
    return v;
}
__device__ __forceinline__ void dp4a(int& acc, uint32_t a, uint32_t b) {
    asm("dp4a.s32.s32 %0, %1, %2, %0;" : "+r"(acc) : "r"(a), "r"(b));
}

// exact rescore: bit-matches reference (verified R2/R4-R9)
__device__ __forceinline__ float exact_d2(const float* __restrict__ cb,
                                          const float* __restrict__ xrow,
                                          float xn, float cnk, int k) {
    const float4* cr = (const float4*)(cb + k * DDIM);
    float s = 0.f;
#pragma unroll 4
    for (int i = 0; i < 16; i++) {
        float4 v = cr[i];
        s = __fmaf_rn(xrow[4 * i + 0], v.x, s);
        s = __fmaf_rn(xrow[4 * i + 1], v.y, s);
        s = __fmaf_rn(xrow[4 * i + 2], v.z, s);
        s = __fmaf_rn(xrow[4 * i + 3], v.w, s);
    }
    return __fadd_rn(__fsub_rn(xn, __fmul_rn(2.0f, s)), cnk);
}

__device__ __forceinline__ void lex_scan_slice(const float* cb, const float* Cn,
                                               const float* xrow, float xn, int w,
                                               float& bv, int& bi) {
#pragma unroll 1
    for (int p = 0; p < PASSES; p++)
#pragma unroll 1
        for (int j = 0; j < 16; j++) {
            int k = p * CPASS + w * 16 + j;
            float d2 = exact_d2(cb, xrow, xn, Cn[k], k);
            if (d2 < bv || (d2 == bv && k < bi)) { bv = d2; bi = k; }
        }
}

__global__ __launch_bounds__(NTHREADS, 1)
void vq_main(const float* __restrict__ h, const float* __restrict__ cb,
             float* __restrict__ outZ, float* __restrict__ outQ) {
    extern __shared__ char smem[];
    float*   Xf   = (float*)(smem + OFF_XF);
    int*     Xi8  = (int*)(smem + OFF_XI8);
    int*     Cs   = (int*)(smem + OFF_CS);
    float*   Cn   = (float*)(smem + OFF_CN);
    int*     cand = (int*)(smem + OFF_CAND);
    float*   redv = (float*)(smem + OFF_REDV);
    float*   gb   = (float*)(smem + OFF_GB);
    float*   rv2  = (float*)(smem + OFF_RV2);
    int*     ri2  = (int*)(smem + OFF_RI2);
    float*   xns  = (float*)(smem + OFF_XNS);
    int*     wix  = (int*)(smem + OFF_WIX);
    uint8_t* sCnt = (uint8_t*)(smem + OFF_SCNT);
    uint8_t* sOfl = (uint8_t*)(smem + OFF_SOFL);
    uint8_t* tOfl = (uint8_t*)(smem + OFF_TOFL);
    const uint32_t sbase = smem_u32(smem);

    const int tid = threadIdx.x;
    const int w = tid >> 5;
    const int l = tid & 31;
    const int n0 = blockIdx.x * TM;
    const int bb_ = n0 >> 12;
    const long base = (long)bb_ * 262144 + (n0 & 4095);

    // ---- Xf [t][65] (exact fp32 for xn + rescore), coalesced d-major gmem reads ----
    for (int i = tid; i < 64 * 32; i += NTHREADS) {
        int d = i >> 5, t4 = i & 31;
        float4 v = *(const float4*)(h + base + (long)d * 4096 + t4 * 4);
        Xf[(t4 * 4 + 0) * 65 + d] = v.x;
        Xf[(t4 * 4 + 1) * 65 + d] = v.y;
        Xf[(t4 * 4 + 2) * 65 + d] = v.z;
        Xf[(t4 * 4 + 3) * 65 + d] = v.w;
    }
    for (int i = tid; i < KCODES; i += NTHREADS) Cn[i] = g_cn[i];
    // load pass-0 code tile
    for (int i = tid; i < 16 * CPASS / 4; i += NTHREADS)
        *(int4*)&Cs[i * 4] = *(const int4*)&g_ci8[(i * 4 / CPASS) * KCODES + ((i * 4) & (CPASS - 1))];
    if (tid < 128) tOfl[tid] = 0;
    for (int i = tid; i < 16 * 128; i += NTHREADS) sOfl[i] = 0;
    __syncthreads();

    // ---- xn exact (sequential mul-then-add, reference order) + quantize X ----
    if (tid < 128) {
        float acc = 0.f;
#pragma unroll
        for (int d = 0; d < 64; d++) {
            float xv = Xf[tid * 65 + d];
            acc = __fadd_rn(acc, __fmul_rn(xv, xv));
        }
        xns[tid] = acc;
    }
    for (int i = tid; i < 16 * 128; i += NTHREADS) {
        int dq = i >> 7, t = i & 127;
        uint32_t p = 0;
        bool bad = false;
#pragma unroll
        for (int e = 0; e < 4; e++) {
            float xv = Xf[t * 65 + dq * 4 + e];
            if (fabsf(xv) > 5.9f) bad = true;
            int v = __float2int_rn(xv * XSCALE);
            v = max(-127, min(127, v));
            p |= ((uint32_t)(uint8_t)(char)v) << (8 * e);
        }
        Xi8[dq * 128 + t] = (int)p;
        if (bad) tOfl[t] = 1;
    }
    __syncthreads();

    const float inv = g_inv;
    const float m2inv = -2.0f * inv;
    float xnr[4];
    {
        float4 v = *(const float4*)&xns[4 * l];
        xnr[0] = v.x; xnr[1] = v.y; xnr[2] = v.z; xnr[3] = v.w;
    }
    float best[4] = {3.4e38f, 3.4e38f, 3.4e38f, 3.4e38f};
    int cnt[4] = {0, 0, 0, 0};

    const uint32_t xaddr = sbase + OFF_XI8 + 16u * l;
    const uint32_t caddr = sbase + OFF_CS + 64u * w;

#pragma unroll 1
    for (int p = 0; p < PASSES; p++) {
        int acc[16][4];
#pragma unroll
        for (int j = 0; j < 16; j++)
#pragma unroll
            for (int t = 0; t < 4; t++) acc[j][t] = 0;

#pragma unroll
        for (int dq = 0; dq < 16; dq++) {
            uint4 x4 = lds128(xaddr + (uint32_t)(dq * 512));
#pragma unroll
            for (int cg = 0; cg < 4; cg++) {
                uint4 c4 = lds128(caddr + (uint32_t)(dq * 1024) + cg * 16);  // warp-uniform
                dp4a(acc[cg * 4 + 0][0], c4.x, x4.x); dp4a(acc[cg * 4 + 0][1], c4.x, x4.y);
                dp4a(acc[cg * 4 + 0][2], c4.x, x4.z); dp4a(acc[cg * 4 + 0][3], c4.x, x4.w);
                dp4a(acc[cg * 4 + 1][0], c4.y, x4.x); dp4a(acc[cg * 4 + 1][1], c4.y, x4.y);
                dp4a(acc[cg * 4 + 1][2], c4.y, x4.z); dp4a(acc[cg * 4 + 1][3], c4.y, x4.w);
                dp4a(acc[cg * 4 + 2][0], c4.z, x4.x); dp4a(acc[cg * 4 + 2][1], c4.z, x4.y);
                dp4a(acc[cg * 4 + 2][2], c4.z, x4.z); dp4a(acc[cg * 4 + 2][3], c4.z, x4.w);
                dp4a(acc[cg * 4 + 3][0], c4.w, x4.x); dp4a(acc[cg * 4 + 3][1], c4.w, x4.y);
                dp4a(acc[cg * 4 + 3][2], c4.w, x4.z); dp4a(acc[cg * 4 + 3][3], c4.w, x4.w);
            }
        }

        // epilogue: approx d2, candidate collection
        const int kw = p * CPASS + w * 16;
#pragma unroll
        for (int j = 0; j < 16; j++) {
            int k = kw + j;
            float cnk = Cn[k];
#pragma unroll
            for (int t = 0; t < 4; t++) {
                float d2a = __fmaf_rn(m2inv, (float)acc[j][t], xnr[t]) + cnk;
                if (d2a < best[t] + MARGIN) {
                    int tok = 4 * l + t;
                    if (cnt[t] < CAP) cand[(w * 128 + tok) * CAP + cnt[t]] = k;
                    else sOfl[w * 128 + tok] = 1;
                    cnt[t]++;
                    if (d2a < best[t]) best[t] = d2a;
                }
            }
        }

        // share best across warps (tightens next pass's thresholds; correctness-safe)
        *(float4*)&redv[w * 128 + 4 * l] = make_float4(best[0], best[1], best[2], best[3]);
        __syncthreads();
        if (tid < 128) {
            float m = redv[tid];
#pragma unroll
            for (int ww = 1; ww < 16; ww++) m = fminf(m, redv[ww * 128 + tid]);
            gb[tid] = m;
        }
        if (p + 1 < PASSES) {  // reload Cs for next pass (Cs idle during reduce)
            for (int i = tid; i < 16 * CPASS / 4; i += NTHREADS) {
                int dq = i * 4 / CPASS, kk = (i * 4) & (CPASS - 1);
                *(int4*)&Cs[i * 4] = *(const int4*)&g_ci8[dq * KCODES + (p + 1) * CPASS + kk];
            }
        }
        __syncthreads();
        {
            float4 gv = *(const float4*)&gb[4 * l];
            best[0] = fminf(best[0], gv.x); best[1] = fminf(best[1], gv.y);
            best[2] = fminf(best[2], gv.z); best[3] = fminf(best[3], gv.w);
        }
    }

#pragma unroll
    for (int t = 0; t < 4; t++)
        sCnt[w * 128 + 4 * l + t] = (uint8_t)min(cnt[t], CAP);
    __syncthreads();

    // ---- exact rescore: 4 threads per token, each covers 4 warps' lists ----
    {
        const int t = tid & 127;
        const int p4 = tid >> 7;
        const float* xrow = &Xf[t * 65];
        const float xn = xns[t];
        float bv = 3.4e38f;
        int bi = 0x7fffffff;
        if (tOfl[t]) {
            for (int ww = p4 * 4; ww < p4 * 4 + 4; ww++)
                lex_scan_slice(cb, Cn, xrow, xn, ww, bv, bi);
        } else {
            for (int ww = p4 * 4; ww < p4 * 4 + 4; ww++) {
                if (sOfl[ww * 128 + t]) {
                    lex_scan_slice(cb, Cn, xrow, xn, ww, bv, bi);
                } else {
                    int n = sCnt[ww * 128 + t];
                    for (int i = 0; i < n; i++) {
                        int k = cand[(ww * 128 + t) * CAP + i];
                        float d2 = exact_d2(cb, xrow, xn, Cn[k], k);
                        if (d2 < bv || (d2 == bv && k < bi)) { bv = d2; bi = k; }
                    }
                }
            }
        }
        rv2[p4 * 128 + t] = bv;
        ri2[p4 * 128 + t] = bi;
    }
    __syncthreads();

    if (tid < 128) {
        float bv = rv2[tid];
        int bi = ri2[tid];
#pragma unroll
        for (int p4 = 1; p4 < 4; p4++) {
            float v = rv2[p4 * 128 + tid];
            int i2 = ri2[p4 * 128 + tid];
            if (v < bv || (v == bv && i2 < bi)) { bv = v; bi = i2; }
        }
        wix[tid] = bi;
        if (outZ) outZ[n0 + tid] = (float)bi;
    }
    __syncthreads();

    // ---- q gather ----
    if (outQ) {
        for (int i = tid; i < 128 * 16; i += NTHREADS) {
            int tt = i >> 4, c4 = i & 15;
            float4 v = *(const float4*)&cb[wix[tt] * DDIM + c4 * 4];
            *(float4*)&outQ[(long)(n0 + tt) * DDIM + c4 * 4] = v;
        }
    }
}

extern "C" void kernel_launch(void* const* d_in, const int* in_sizes, int n_in,
                              void* d_out, int out_size) {
    const float* h = (const float*)d_in[0];
    const float* cb = (const float*)d_in[1];
    float* out = (float*)d_out;

    float* outZ = nullptr;
    float* outQ = nullptr;
    if (out_size >= NTOK + NTOK * DDIM) { outZ = out; outQ = out + NTOK; }
    else if (out_size == NTOK * DDIM)   { outQ = out; }
    else                                { outZ = out; }

    cudaFuncSetAttribute(vq_main, cudaFuncAttributeMaxDynamicSharedMemorySize, SMEM_BYTES);
    vq_prep1<<<16, 256>>>(cb);
    vq_prep2<<<4, 256>>>(cb);
    vq_main<<<NTOK / TM, NTHREADS, SMEM_BYTES>>>(h, cb, outZ, outQ);
}